// round 10
// baseline (speedup 1.0000x reference)
#include <cuda_runtime.h>
#include <cstdint>
#include <cstddef>

#define B_  64
#define T_  512
#define I_  256
#define H_  512
#define G4  2048   // 4*H
#define O_  256

#define NCTA_SCAN 128
#define NTHR_SCAN 512

// ---------------- static scratch (allocation-free per rules) ----------------
__device__ float g_xp[(size_t)B_ * T_ * G4];     // x@W + bias, [B*T, 4H]
__device__ float g_hseq[(size_t)B_ * T_ * H_];   // hidden_seq [B*T, H]
__device__ float g_hbuf[2][H_ * B_];             // h double buffer, [hc][pair rp] = [k][b] pairs
__device__ unsigned g_bar;

// ---------------- packed fp32x2 helpers (sm_103 FFMA2) ----------------
__device__ __forceinline__ unsigned long long pk2(float x, float y) {
    unsigned long long r;
    asm("mov.b64 %0, {%1,%2};" : "=l"(r) : "f"(x), "f"(y));
    return r;
}
__device__ __forceinline__ void fma2(unsigned long long& d, unsigned long long a, unsigned long long b) {
    asm("fma.rn.f32x2 %0, %1, %2, %0;" : "+l"(d) : "l"(a), "l"(b));
}
__device__ __forceinline__ float2 up2(unsigned long long v) {
    float lo, hi;
    asm("mov.b64 {%0,%1}, %2;" : "=f"(lo), "=f"(hi) : "l"(v));
    return make_float2(lo, hi);
}
__device__ __forceinline__ float sigmoidf_(float x) { return 1.0f / (1.0f + expf(-x)); }

// ---------------- init: zero h0 + barrier counter ----------------
__global__ void init_kernel() {
    int i = blockIdx.x * blockDim.x + threadIdx.x;
    if (i < H_ * B_) g_hbuf[0][i] = 0.0f;
    if (i == 0) g_bar = 0u;
}

// ---------------- fp32 GEMM + bias (FFMA2), 128x128x16 tiles ----------------
__global__ void __launch_bounds__(256) gemm_bias(const float* __restrict__ A,
                                                 const float* __restrict__ Bm,
                                                 const float* __restrict__ bias,
                                                 float* __restrict__ C,
                                                 int M, int N, int K) {
    __shared__ float As[16][128];
    __shared__ float Bs[16][128];
    const int tid = threadIdx.x;
    const int bm = blockIdx.y * 128, bn = blockIdx.x * 128;
    const int tx = tid & 15, ty = tid >> 4;

    unsigned long long acc[8][4];
#pragma unroll
    for (int i = 0; i < 8; i++)
#pragma unroll
        for (int j = 0; j < 4; j++) acc[i][j] = 0ull;

    const int ar = tid >> 2, akq = tid & 3;
    const int br = tid >> 5, bc = tid & 31;

    for (int k0 = 0; k0 < K; k0 += 16) {
#pragma unroll
        for (int i = 0; i < 2; i++) {
            int r = ar + i * 64;
            float4 v = *(const float4*)&A[(size_t)(bm + r) * K + k0 + akq * 4];
            As[akq * 4 + 0][r] = v.x; As[akq * 4 + 1][r] = v.y;
            As[akq * 4 + 2][r] = v.z; As[akq * 4 + 3][r] = v.w;
        }
#pragma unroll
        for (int i = 0; i < 2; i++) {
            int rr = br + i * 8;
            *(float4*)&Bs[rr][bc * 4] =
                *(const float4*)&Bm[(size_t)(k0 + rr) * N + bn + bc * 4];
        }
        __syncthreads();
#pragma unroll
        for (int kk = 0; kk < 16; kk++) {
            float4 a0 = *(const float4*)&As[kk][ty * 8];
            float4 a1 = *(const float4*)&As[kk][ty * 8 + 4];
            ulonglong2 b0 = *(const ulonglong2*)&Bs[kk][tx * 8];
            ulonglong2 b1 = *(const ulonglong2*)&Bs[kk][tx * 8 + 4];
            float aa[8] = {a0.x, a0.y, a0.z, a0.w, a1.x, a1.y, a1.z, a1.w};
#pragma unroll
            for (int i = 0; i < 8; i++) {
                unsigned long long ap = pk2(aa[i], aa[i]);
                fma2(acc[i][0], ap, b0.x);
                fma2(acc[i][1], ap, b0.y);
                fma2(acc[i][2], ap, b1.x);
                fma2(acc[i][3], ap, b1.y);
            }
        }
        __syncthreads();
    }

    float4 bsa = *(const float4*)&bias[bn + tx * 8];
    float4 bsb = *(const float4*)&bias[bn + tx * 8 + 4];
#pragma unroll
    for (int i = 0; i < 8; i++) {
        float2 p0 = up2(acc[i][0]), p1 = up2(acc[i][1]);
        float2 p2 = up2(acc[i][2]), p3 = up2(acc[i][3]);
        float4 o0 = make_float4(p0.x + bsa.x, p0.y + bsa.y, p1.x + bsa.z, p1.y + bsa.w);
        float4 o1 = make_float4(p2.x + bsb.x, p2.y + bsb.y, p3.x + bsb.z, p3.y + bsb.w);
        size_t m = (size_t)(bm + ty * 8 + i);
        *(float4*)&C[m * N + bn + tx * 8]     = o0;
        *(float4*)&C[m * N + bn + tx * 8 + 4] = o1;
    }
}

// ---------------- persistent LSTM scan (register-tiled FFMA2, K-split 8) ----------------
// 128 CTAs x 512 threads (16 warps). CTA owns hidden cols [4cta, 4cta+4) -> 16 gate
// cols, n = q*4+g. Warp w: kslice = w>>1 (K chunk of 64), half = w&1 (gate cols
// half*8 .. half*8+8). Lane: rg = lane&7 (rows 8rg..8rg+7 = pairs 4rg..4rg+3),
// gg = lane>>3 -> gates base = half*8 + 2*gg (+0,+1).
// Thread inner iter: 2x LDS.128 (h pairs) + 1x LDS.128 (dup'd U pair2, warp-broadcast)
// feeding 8 FFMA2 -> 48 smem bytes / 16 MACs. Partials (8 K-slices) reduced in smem
// by 128 cell threads (thread = (q, rp): rows 2rp,2rp+1, hidden col 4cta+q).
//
// smem (bytes): [0, 65536)       U_s  : [512 k][16 n] dup pairs (u,u)
//               [65536, 196608)  h_s  : [512 k][32 row-pairs] float2
//               [196608, 230400) part : [8 ks][16 n][33 pitch] float2
#define SMO_U   0
#define SMO_H   65536
#define SMO_P   196608
#define SCAN_SMEM 230400

__global__ void __launch_bounds__(NTHR_SCAN, 1)
lstm_scan(const float* __restrict__ U, float* __restrict__ dout) {
    extern __shared__ char smem[];
    unsigned long long* Ud = (unsigned long long*)(smem + SMO_U);   // pair index (k*16+n)
    float*              hS = (float*)(smem + SMO_H);                // float idx (k*32+rp)*2
    float2*             pt = (float2*)(smem + SMO_P);               // (ks*16+n)*33+rp

    const int tid  = threadIdx.x;
    const int lane = tid & 31;
    const int wid  = tid >> 5;
    const int cta  = blockIdx.x;

    const int ks   = wid >> 1;
    const int half = wid & 1;
    const int rg   = lane & 7;
    const int gg   = lane >> 3;
    const int base = half * 8 + gg * 2;     // gate cols base, base+1

    // ---- one-time: gather U slice, duplicated (u,u) for FFMA2 ----
    for (int idx = tid; idx < 512 * 16; idx += NTHR_SCAN) {
        int k = idx >> 4, n = idx & 15;
        int q = n >> 2, g = n & 3;
        float u = U[(size_t)k * G4 + g * H_ + 4 * cta + q];
        Ud[idx] = pk2(u, u);
    }

    // cell-thread state
    const int cq = tid >> 5;          // valid when tid<128: hidden col local
    const int rp = tid & 31;          // row pair
    const int hc = 4 * cta + cq;
    float cc0 = 0.0f, cc1 = 0.0f;
    const size_t OUT_ELEMS = (size_t)B_ * T_ * O_;

    const ulonglong2* hV = (const ulonglong2*)hS;   // idx k*16 + 2rg (+1)
    const ulonglong2* uV = (const ulonglong2*)Ud;   // idx k*8 + base/2
    const int hbaseA = 2 * rg;
    const int ubase  = base >> 1;

    for (int s = 0; s < T_; s++) {
        // ---- xp prefetch into registers (cell threads), overlaps staging ----
        float xg0[4], xg1[4];
        if (tid < 128) {
            const float* xp0 = g_xp + ((size_t)(2 * rp) * T_ + s) * G4 + hc;
            const float* xp1 = xp0 + (size_t)T_ * G4;
#pragma unroll
            for (int g = 0; g < 4; g++) {
                xg0[g] = __ldcg(xp0 + g * H_);
                xg1[g] = __ldcg(xp1 + g * H_);
            }
        }

        // ---- stage h: straight 128KB copy, L2 -> smem (bypass L1) ----
        {
            const float4* src = (const float4*)g_hbuf[s & 1];
            float4* dst = (float4*)hS;
#pragma unroll
            for (int i = 0; i < 8192 / NTHR_SCAN; i++)
                dst[tid + i * NTHR_SCAN] = __ldcg(&src[tid + i * NTHR_SCAN]);
        }
        __syncthreads();

        // ---- main loop: K chunk of 64, 8 FFMA2 per k ----
        unsigned long long a00 = 0, a01 = 0, a10 = 0, a11 = 0,
                           a20 = 0, a21 = 0, a30 = 0, a31 = 0;
        const int k0 = ks * 64;
#pragma unroll 4
        for (int k = k0; k < k0 + 64; k++) {
            ulonglong2 hA = hV[k * 16 + hbaseA];
            ulonglong2 hB = hV[k * 16 + hbaseA + 1];
            ulonglong2 uu = uV[k * 8 + ubase];
            fma2(a00, hA.x, uu.x); fma2(a01, hA.x, uu.y);
            fma2(a10, hA.y, uu.x); fma2(a11, hA.y, uu.y);
            fma2(a20, hB.x, uu.x); fma2(a21, hB.x, uu.y);
            fma2(a30, hB.y, uu.x); fma2(a31, hB.y, uu.y);
        }

        // ---- write partials: part[ks][n][4rg+j] ----
        {
            float2* p0 = &pt[(ks * 16 + base) * 33 + 4 * rg];
            float2* p1 = &pt[(ks * 16 + base + 1) * 33 + 4 * rg];
            p0[0] = up2(a00); p1[0] = up2(a01);
            p0[1] = up2(a10); p1[1] = up2(a11);
            p0[2] = up2(a20); p1[2] = up2(a21);
            p0[3] = up2(a30); p1[3] = up2(a31);
        }
        __syncthreads();

        // ---- cell: reduce 8 K-slices, activations, writes ----
        if (tid < 128) {
            float gt0[4], gt1[4];
#pragma unroll
            for (int g = 0; g < 4; g++) {
                int n = cq * 4 + g;
                float sx = xg0[g], sy = xg1[g];
#pragma unroll
                for (int kk = 0; kk < 8; kk++) {
                    float2 p = pt[(kk * 16 + n) * 33 + rp];
                    sx += p.x; sy += p.y;
                }
                gt0[g] = sx; gt1[g] = sy;
            }
            float i0 = sigmoidf_(gt0[0]), i1 = sigmoidf_(gt1[0]);
            float f0 = sigmoidf_(gt0[1]), f1 = sigmoidf_(gt1[1]);
            float g0 = tanhf(gt0[2]),     g1 = tanhf(gt1[2]);
            float o0 = sigmoidf_(gt0[3]), o1 = sigmoidf_(gt1[3]);
            cc0 = f0 * cc0 + i0 * g0;
            cc1 = f1 * cc1 + i1 * g1;
            float h0n = o0 * tanhf(cc0);
            float h1n = o1 * tanhf(cc1);

            // next-step h buffer ([hc][rp] pairs, coalesced)
            ((float2*)g_hbuf[(s + 1) & 1])[hc * 32 + rp] = make_float2(h0n, h1n);
            // hidden_seq fp32 [b][t][h]
            g_hseq[(size_t)(2 * rp * T_ + s) * H_ + hc]       = h0n;
            g_hseq[(size_t)((2 * rp + 1) * T_ + s) * H_ + hc] = h1n;

            if (s == T_ - 1) {
                dout[OUT_ELEMS + (size_t)(2 * rp) * H_ + hc]     = h0n;
                dout[OUT_ELEMS + (size_t)(2 * rp + 1) * H_ + hc] = h1n;
                dout[OUT_ELEMS + (size_t)B_ * H_ + (size_t)(2 * rp) * H_ + hc]     = cc0;
                dout[OUT_ELEMS + (size_t)B_ * H_ + (size_t)(2 * rp + 1) * H_ + hc] = cc1;
            }
        }

        // ---- grid barrier (128 CTAs, all resident) ----
        __threadfence();
        __syncthreads();
        if (tid == 0) {
            atomicAdd(&g_bar, 1u);
            unsigned target = (unsigned)NCTA_SCAN * (unsigned)(s + 1);
            while (*(volatile unsigned*)&g_bar < target) { }
            __threadfence();
        }
        __syncthreads();
    }
}

// ---------------- launch ----------------
extern "C" void kernel_launch(void* const* d_in, const int* in_sizes, int n_in,
                              void* d_out, int out_size) {
    const float* x    = (const float*)d_in[0];
    const float* W    = (const float*)d_in[1];
    const float* U    = (const float*)d_in[2];
    const float* bias = (const float*)d_in[3];
    const float* Wl   = (const float*)d_in[4];
    const float* bl   = (const float*)d_in[5];
    float* out = (float*)d_out;

    void* xp_ptr = nullptr;
    void* hs_ptr = nullptr;
    cudaGetSymbolAddress(&xp_ptr, g_xp);
    cudaGetSymbolAddress(&hs_ptr, g_hseq);

    cudaFuncSetAttribute(lstm_scan, cudaFuncAttributeMaxDynamicSharedMemorySize, SCAN_SMEM);

    // 1) reset h0 / barrier
    init_kernel<<<128, 256>>>();
    // 2) x_proj = x @ W + bias : [32768,256]@[256,2048]
    gemm_bias<<<dim3(G4 / 128, (B_ * T_) / 128), 256>>>(x, W, bias, (float*)xp_ptr,
                                                        B_ * T_, G4, I_);
    // 3) recurrent scan (persistent, 512 steps)
    lstm_scan<<<NCTA_SCAN, NTHR_SCAN, SCAN_SMEM>>>(U, out);
    // 4) out = hidden_seq @ Wl + bl : [32768,512]@[512,256]
    gemm_bias<<<dim3(O_ / 128, (B_ * T_) / 128), 256>>>((const float*)hs_ptr, Wl, bl, out,
                                                        B_ * T_, O_, H_);
}

// round 11
// speedup vs baseline: 1.7732x; 1.7732x over previous
#include <cuda_runtime.h>
#include <cuda_fp16.h>
#include <cstdint>
#include <cstddef>

#define B_  64
#define T_  512
#define I_  256
#define H_  512
#define G4  2048   // 4*H
#define O_  256

#define NCTA_SCAN 64
#define NTHR_SCAN 256
#define PITCH 520          // fp16 pitch for mma operand tiles (65*16B rows)
#define PADC  36           // gates smem col pad

// ---------------- static scratch ----------------
__device__ float  g_xp[(size_t)B_ * T_ * G4];     // x@W + bias, [B*T, 4H]
__device__ float  g_hseq[(size_t)B_ * T_ * H_];   // hidden_seq [B*T, H]
__device__ __half g_hhi[2][B_ * H_];              // h hi plane, [b][k]
__device__ __half g_hlo[2][B_ * H_];              // h lo plane, [b][k]
__device__ unsigned g_bar;

// ---------------- packed fp32x2 helpers (FFMA2, for the GEMMs) ----------------
__device__ __forceinline__ unsigned long long pk2(float x, float y) {
    unsigned long long r;
    asm("mov.b64 %0, {%1,%2};" : "=l"(r) : "f"(x), "f"(y));
    return r;
}
__device__ __forceinline__ void fma2(unsigned long long& d, unsigned long long a, unsigned long long b) {
    asm("fma.rn.f32x2 %0, %1, %2, %0;" : "+l"(d) : "l"(a), "l"(b));
}
__device__ __forceinline__ float2 up2(unsigned long long v) {
    float lo, hi;
    asm("mov.b64 {%0,%1}, %2;" : "=f"(lo), "=f"(hi) : "l"(v));
    return make_float2(lo, hi);
}
__device__ __forceinline__ float sigmoidf_(float x) { return 1.0f / (1.0f + expf(-x)); }

__device__ __forceinline__ uint32_t smem_u32(const void* p) {
    uint32_t a;
    asm("{ .reg .u64 t; cvta.to.shared.u64 t, %1; cvt.u32.u64 %0, t; }" : "=r"(a) : "l"(p));
    return a;
}
__device__ __forceinline__ void ldmx4(uint32_t* r, uint32_t addr) {
    asm volatile("ldmatrix.sync.aligned.m8n8.x4.shared.b16 {%0,%1,%2,%3}, [%4];"
                 : "=r"(r[0]), "=r"(r[1]), "=r"(r[2]), "=r"(r[3]) : "r"(addr));
}
__device__ __forceinline__ void mma16816(float* d, const uint32_t* a, uint32_t b0, uint32_t b1) {
    asm volatile(
        "mma.sync.aligned.m16n8k16.row.col.f32.f16.f16.f32 "
        "{%0,%1,%2,%3}, {%4,%5,%6,%7}, {%8,%9}, {%0,%1,%2,%3};"
        : "+f"(d[0]), "+f"(d[1]), "+f"(d[2]), "+f"(d[3])
        : "r"(a[0]), "r"(a[1]), "r"(a[2]), "r"(a[3]), "r"(b0), "r"(b1));
}

// ---------------- init ----------------
__global__ void init_kernel() {
    int i = blockIdx.x * blockDim.x + threadIdx.x;
    if (i < (B_ * H_) / 2) {
        ((uint32_t*)g_hhi[0])[i] = 0u;
        ((uint32_t*)g_hlo[0])[i] = 0u;
    }
    if (i == 0) g_bar = 0u;
}

// ---------------- fp32 GEMM + bias (FFMA2), proven ----------------
__global__ void __launch_bounds__(256) gemm_bias(const float* __restrict__ A,
                                                 const float* __restrict__ Bm,
                                                 const float* __restrict__ bias,
                                                 float* __restrict__ C,
                                                 int M, int N, int K) {
    __shared__ float As[16][128];
    __shared__ float Bs[16][128];
    const int tid = threadIdx.x;
    const int bm = blockIdx.y * 128, bn = blockIdx.x * 128;
    const int tx = tid & 15, ty = tid >> 4;

    unsigned long long acc[8][4];
#pragma unroll
    for (int i = 0; i < 8; i++)
#pragma unroll
        for (int j = 0; j < 4; j++) acc[i][j] = 0ull;

    const int ar = tid >> 2, akq = tid & 3;
    const int br = tid >> 5, bc = tid & 31;

    for (int k0 = 0; k0 < K; k0 += 16) {
#pragma unroll
        for (int i = 0; i < 2; i++) {
            int r = ar + i * 64;
            float4 v = *(const float4*)&A[(size_t)(bm + r) * K + k0 + akq * 4];
            As[akq * 4 + 0][r] = v.x; As[akq * 4 + 1][r] = v.y;
            As[akq * 4 + 2][r] = v.z; As[akq * 4 + 3][r] = v.w;
        }
#pragma unroll
        for (int i = 0; i < 2; i++) {
            int rr = br + i * 8;
            *(float4*)&Bs[rr][bc * 4] =
                *(const float4*)&Bm[(size_t)(k0 + rr) * N + bn + bc * 4];
        }
        __syncthreads();
#pragma unroll
        for (int kk = 0; kk < 16; kk++) {
            float4 a0 = *(const float4*)&As[kk][ty * 8];
            float4 a1 = *(const float4*)&As[kk][ty * 8 + 4];
            ulonglong2 b0 = *(const ulonglong2*)&Bs[kk][tx * 8];
            ulonglong2 b1 = *(const ulonglong2*)&Bs[kk][tx * 8 + 4];
            float aa[8] = {a0.x, a0.y, a0.z, a0.w, a1.x, a1.y, a1.z, a1.w};
#pragma unroll
            for (int i = 0; i < 8; i++) {
                unsigned long long ap = pk2(aa[i], aa[i]);
                fma2(acc[i][0], ap, b0.x);
                fma2(acc[i][1], ap, b0.y);
                fma2(acc[i][2], ap, b1.x);
                fma2(acc[i][3], ap, b1.y);
            }
        }
        __syncthreads();
    }

    float4 bsa = *(const float4*)&bias[bn + tx * 8];
    float4 bsb = *(const float4*)&bias[bn + tx * 8 + 4];
#pragma unroll
    for (int i = 0; i < 8; i++) {
        float2 p0 = up2(acc[i][0]), p1 = up2(acc[i][1]);
        float2 p2 = up2(acc[i][2]), p3 = up2(acc[i][3]);
        float4 o0 = make_float4(p0.x + bsa.x, p0.y + bsa.y, p1.x + bsa.z, p1.y + bsa.w);
        float4 o1 = make_float4(p2.x + bsb.x, p2.y + bsb.y, p3.x + bsb.z, p3.y + bsb.w);
        size_t m = (size_t)(bm + ty * 8 + i);
        *(float4*)&C[m * N + bn + tx * 8]     = o0;
        *(float4*)&C[m * N + bn + tx * 8 + 4] = o1;
    }
}

// ---------------- mma.sync persistent LSTM scan ----------------
// 64 CTAs x 256 thr. CTA owns hidden cols [8cta, 8cta+8) -> 32 gate cols, n = g*8+q.
// Per step: gates[64,32] = h_hi@U_hi + h_lo@U_hi + h_hi@U_lo  (fp16 in, fp32 acc).
// 8 warps = (mg 2) x (ng 2) x (kh 2); warp computes 2x2 m16n8 tiles over 16 k-tiles.
// smem byte offsets:
#define SM_AH  0
#define SM_AL  66560
#define SM_UH  133120
#define SM_UL  166400
#define SM_GT  199680           // 2 x [64][PADC] f32 (kh partials)
#define SM_XP  218112           // [64][32] f32
#define SCAN_SMEM 226304

__global__ void __launch_bounds__(NTHR_SCAN, 1)
lstm_scan(const float* __restrict__ U, float* __restrict__ dout) {
    extern __shared__ char smem[];
    const uint32_t sb = smem_u32(smem);
    const int tid  = threadIdx.x;
    const int lane = tid & 31;
    const int wid  = tid >> 5;
    const int cta  = blockIdx.x;

    // ---- one-time: gather U slice -> hi/lo fp16 planes [n][k], pitch 520 ----
    for (int idx = tid; idx < 32 * 512; idx += NTHR_SCAN) {
        int n = idx & 31, k = idx >> 5;
        int g = n >> 3, q = n & 7;
        float u = U[(size_t)k * G4 + g * H_ + 8 * cta + q];
        __half uhi = __float2half_rn(u);
        __half ulo = __float2half_rn(u - __half2float(uhi));
        *(__half*)(smem + SM_UH + ((size_t)n * PITCH + k) * 2) = uhi;
        *(__half*)(smem + SM_UL + ((size_t)n * PITCH + k) * 2) = ulo;
    }

    // warp roles
    const int mg = wid & 1;
    const int ng = (wid >> 1) & 1;
    const int kh = wid >> 2;

    // ldmatrix per-lane byte offsets (within a plane)
    // A: row = mg*32 + mi*16 + (lane&15); +16B if lane>=16 (k+8)
    uint32_t aoff[2];
#pragma unroll
    for (int mi = 0; mi < 2; mi++)
        aoff[mi] = (uint32_t)((mg * 32 + mi * 16 + (lane & 15)) * PITCH * 2 + (lane >> 4) * 16);
    // B (x4 covering 2 n-tiles): sub = lane>>3: row = ng*16 + (sub>>1)*8 + (lane&7); k8 if sub&1
    const int sub = lane >> 3;
    const uint32_t boff = (uint32_t)((ng * 16 + (sub >> 1) * 8 + (lane & 7)) * PITCH * 2 + (sub & 1) * 16);

    // cell-thread state: pairs p = tid, tid+256 ; p -> b = p>>3, q = p&7
    float cst[2] = {0.0f, 0.0f};
    const size_t OUT_ELEMS = (size_t)B_ * T_ * O_;

    __syncthreads();

    for (int s = 0; s < T_; s++) {
        // ---- stage h hi/lo planes: [b][512] fp16 -> smem pitch 520 ----
        {
            const uint4* s0 = (const uint4*)g_hhi[s & 1];
            const uint4* s1 = (const uint4*)g_hlo[s & 1];
#pragma unroll
            for (int i = 0; i < 16; i++) {
                int j = tid + i * NTHR_SCAN;           // 0..4095: row=j>>6, chunk=j&63
                uint32_t off = (uint32_t)((j >> 6) * (PITCH * 2) + (j & 63) * 16);
                *(uint4*)(smem + SM_AH + off) = __ldcg(&s0[j]);
                *(uint4*)(smem + SM_AL + off) = __ldcg(&s1[j]);
            }
        }
        // ---- xp -> smem [b][32] (coalesced) ----
        {
            int b = tid >> 2, g = tid & 3;
            const float4* xs = (const float4*)(g_xp + ((size_t)b * T_ + s) * G4 + (size_t)g * H_ + 8 * cta);
            float4 v0 = __ldcg(xs);
            float4 v1 = __ldcg(xs + 1);
            float* xp = (float*)(smem + SM_XP) + b * 32 + g * 8;
            *(float4*)xp       = v0;
            *(float4*)(xp + 4) = v1;
        }
        __syncthreads();

        // ---- 3 passes of m16n8k16 MMAs ----
        float ac[16];
#pragma unroll
        for (int i = 0; i < 16; i++) ac[i] = 0.0f;

#pragma unroll
        for (int p = 0; p < 3; p++) {
            const uint32_t Ab = sb + ((p == 1) ? SM_AL : SM_AH);
            const uint32_t Bb = sb + ((p == 2) ? SM_UL : SM_UH);
            const int kt0 = kh * 16;
#pragma unroll 4
            for (int kt = kt0; kt < kt0 + 16; kt++) {
                uint32_t kb = (uint32_t)kt * 32;
                uint32_t a0[4], a1[4], bb[4];
                ldmx4(a0, Ab + aoff[0] + kb);
                ldmx4(a1, Ab + aoff[1] + kb);
                ldmx4(bb, Bb + boff + kb);
                mma16816(ac + 0,  a0, bb[0], bb[1]);   // (m0, n0)
                mma16816(ac + 4,  a0, bb[2], bb[3]);   // (m0, n1)
                mma16816(ac + 8,  a1, bb[0], bb[1]);   // (m1, n0)
                mma16816(ac + 12, a1, bb[2], bb[3]);   // (m1, n1)
            }
        }

        // ---- write kh-partials to gates smem ----
        {
            float* GT = (float*)(smem + SM_GT) + (size_t)kh * 64 * PADC;
            int r = lane >> 2, cbase = (lane & 3) * 2;
#pragma unroll
            for (int mi = 0; mi < 2; mi++)
#pragma unroll
                for (int ni = 0; ni < 2; ni++) {
                    const float* a = ac + mi * 8 + ni * 4;
                    int row = mg * 32 + mi * 16 + r;
                    int col = ng * 16 + ni * 8 + cbase;
                    *(float2*)&GT[row * PADC + col]       = make_float2(a[0], a[1]);
                    *(float2*)&GT[(row + 8) * PADC + col] = make_float2(a[2], a[3]);
                }
        }
        __syncthreads();

        // ---- cell: 256 threads x 2 (b,q) pairs ----
        {
            const float* GT0 = (float*)(smem + SM_GT);
            const float* GT1 = GT0 + 64 * PADC;
            const float* XP  = (float*)(smem + SM_XP);
#pragma unroll
            for (int rep = 0; rep < 2; rep++) {
                int p = tid + rep * 256;
                int b = p >> 3, q = p & 7;
                float gt[4];
#pragma unroll
                for (int g = 0; g < 4; g++) {
                    int col = g * 8 + q;
                    gt[g] = GT0[b * PADC + col] + GT1[b * PADC + col] + XP[b * 32 + col];
                }
                float gi = sigmoidf_(gt[0]);
                float gf = sigmoidf_(gt[1]);
                float gg = tanhf(gt[2]);
                float go = sigmoidf_(gt[3]);
                float cn = gf * cst[rep] + gi * gg;
                cst[rep] = cn;
                float hn = go * tanhf(cn);

                int hidx = 8 * cta + q;
                g_hseq[((size_t)b * T_ + s) * H_ + hidx] = hn;
                __half hh = __float2half_rn(hn);
                __half hl = __float2half_rn(hn - __half2float(hh));
                g_hhi[(s + 1) & 1][b * H_ + hidx] = hh;
                g_hlo[(s + 1) & 1][b * H_ + hidx] = hl;

                if (s == T_ - 1) {
                    dout[OUT_ELEMS + (size_t)b * H_ + hidx] = hn;
                    dout[OUT_ELEMS + (size_t)B_ * H_ + (size_t)b * H_ + hidx] = cn;
                }
            }
        }

        // ---- grid barrier (64 CTAs, all resident) ----
        __threadfence();
        __syncthreads();
        if (tid == 0) {
            atomicAdd(&g_bar, 1u);
            unsigned target = (unsigned)NCTA_SCAN * (unsigned)(s + 1);
            while (*(volatile unsigned*)&g_bar < target) { }
            __threadfence();
        }
        __syncthreads();
    }
}

// ---------------- launch ----------------
extern "C" void kernel_launch(void* const* d_in, const int* in_sizes, int n_in,
                              void* d_out, int out_size) {
    const float* x    = (const float*)d_in[0];
    const float* W    = (const float*)d_in[1];
    const float* U    = (const float*)d_in[2];
    const float* bias = (const float*)d_in[3];
    const float* Wl   = (const float*)d_in[4];
    const float* bl   = (const float*)d_in[5];
    float* out = (float*)d_out;

    void* xp_ptr = nullptr;
    void* hs_ptr = nullptr;
    cudaGetSymbolAddress(&xp_ptr, g_xp);
    cudaGetSymbolAddress(&hs_ptr, g_hseq);

    cudaFuncSetAttribute(lstm_scan, cudaFuncAttributeMaxDynamicSharedMemorySize, SCAN_SMEM);

    // 1) reset h0 planes / barrier
    init_kernel<<<128, 256>>>();
    // 2) x_proj = x @ W + bias : [32768,256]@[256,2048]
    gemm_bias<<<dim3(G4 / 128, (B_ * T_) / 128), 256>>>(x, W, bias, (float*)xp_ptr,
                                                        B_ * T_, G4, I_);
    // 3) recurrent scan (mma.sync fp16-split, persistent, 512 steps)
    lstm_scan<<<NCTA_SCAN, NTHR_SCAN, SCAN_SMEM>>>(U, out);
    // 4) out = hidden_seq @ Wl + bl : [32768,512]@[512,256]
    gemm_bias<<<dim3(O_ / 128, (B_ * T_) / 128), 256>>>((const float*)hs_ptr, Wl, bl, out,
                                                        B_ * T_, O_, H_);
}

// round 12
// speedup vs baseline: 2.4082x; 1.3581x over previous
#include <cuda_runtime.h>
#include <cuda_fp16.h>
#include <cstdint>
#include <cstddef>

#define B_  64
#define T_  512
#define I_  256
#define H_  512
#define G4  2048   // 4*H
#define O_  256

#define NCTA_SCAN 128
#define NTHR_SCAN 256
#define PITCH 520          // fp16 pitch for mma operand tiles (65*16B rows -> conflict-free)
#define PADC  20           // gates smem col pad (16 + 4)

// ---------------- static scratch ----------------
__device__ float  g_xp[(size_t)B_ * T_ * G4];     // x@W + bias, [B*T, 4H]
__device__ float  g_hseq[(size_t)B_ * T_ * H_];   // hidden_seq [B*T, H]
__device__ __half g_hhi[2][B_ * H_];              // h hi plane, [b][k]
__device__ __half g_hlo[2][B_ * H_];              // h lo plane, [b][k]
__device__ unsigned g_bar;

// ---------------- packed fp32x2 helpers (FFMA2, for the GEMMs) ----------------
__device__ __forceinline__ unsigned long long pk2(float x, float y) {
    unsigned long long r;
    asm("mov.b64 %0, {%1,%2};" : "=l"(r) : "f"(x), "f"(y));
    return r;
}
__device__ __forceinline__ void fma2(unsigned long long& d, unsigned long long a, unsigned long long b) {
    asm("fma.rn.f32x2 %0, %1, %2, %0;" : "+l"(d) : "l"(a), "l"(b));
}
__device__ __forceinline__ float2 up2(unsigned long long v) {
    float lo, hi;
    asm("mov.b64 {%0,%1}, %2;" : "=f"(lo), "=f"(hi) : "l"(v));
    return make_float2(lo, hi);
}
__device__ __forceinline__ float sigmoidf_(float x) { return 1.0f / (1.0f + expf(-x)); }

__device__ __forceinline__ uint32_t smem_u32(const void* p) {
    uint32_t a;
    asm("{ .reg .u64 t; cvta.to.shared.u64 t, %1; cvt.u32.u64 %0, t; }" : "=r"(a) : "l"(p));
    return a;
}
__device__ __forceinline__ void ldmx4(uint32_t* r, uint32_t addr) {
    asm volatile("ldmatrix.sync.aligned.m8n8.x4.shared.b16 {%0,%1,%2,%3}, [%4];"
                 : "=r"(r[0]), "=r"(r[1]), "=r"(r[2]), "=r"(r[3]) : "r"(addr));
}
__device__ __forceinline__ void mma16816(float* d, const uint32_t* a, uint32_t b0, uint32_t b1) {
    asm volatile(
        "mma.sync.aligned.m16n8k16.row.col.f32.f16.f16.f32 "
        "{%0,%1,%2,%3}, {%4,%5,%6,%7}, {%8,%9}, {%0,%1,%2,%3};"
        : "+f"(d[0]), "+f"(d[1]), "+f"(d[2]), "+f"(d[3])
        : "r"(a[0]), "r"(a[1]), "r"(a[2]), "r"(a[3]), "r"(b0), "r"(b1));
}

// ---------------- init ----------------
__global__ void init_kernel() {
    int i = blockIdx.x * blockDim.x + threadIdx.x;
    if (i < (B_ * H_) / 2) {
        ((uint32_t*)g_hhi[0])[i] = 0u;
        ((uint32_t*)g_hlo[0])[i] = 0u;
    }
    if (i == 0) g_bar = 0u;
}

// ---------------- fp32 GEMM + bias (FFMA2), proven ----------------
__global__ void __launch_bounds__(256) gemm_bias(const float* __restrict__ A,
                                                 const float* __restrict__ Bm,
                                                 const float* __restrict__ bias,
                                                 float* __restrict__ C,
                                                 int M, int N, int K) {
    __shared__ float As[16][128];
    __shared__ float Bs[16][128];
    const int tid = threadIdx.x;
    const int bm = blockIdx.y * 128, bn = blockIdx.x * 128;
    const int tx = tid & 15, ty = tid >> 4;

    unsigned long long acc[8][4];
#pragma unroll
    for (int i = 0; i < 8; i++)
#pragma unroll
        for (int j = 0; j < 4; j++) acc[i][j] = 0ull;

    const int ar = tid >> 2, akq = tid & 3;
    const int br = tid >> 5, bc = tid & 31;

    for (int k0 = 0; k0 < K; k0 += 16) {
#pragma unroll
        for (int i = 0; i < 2; i++) {
            int r = ar + i * 64;
            float4 v = *(const float4*)&A[(size_t)(bm + r) * K + k0 + akq * 4];
            As[akq * 4 + 0][r] = v.x; As[akq * 4 + 1][r] = v.y;
            As[akq * 4 + 2][r] = v.z; As[akq * 4 + 3][r] = v.w;
        }
#pragma unroll
        for (int i = 0; i < 2; i++) {
            int rr = br + i * 8;
            *(float4*)&Bs[rr][bc * 4] =
                *(const float4*)&Bm[(size_t)(k0 + rr) * N + bn + bc * 4];
        }
        __syncthreads();
#pragma unroll
        for (int kk = 0; kk < 16; kk++) {
            float4 a0 = *(const float4*)&As[kk][ty * 8];
            float4 a1 = *(const float4*)&As[kk][ty * 8 + 4];
            ulonglong2 b0 = *(const ulonglong2*)&Bs[kk][tx * 8];
            ulonglong2 b1 = *(const ulonglong2*)&Bs[kk][tx * 8 + 4];
            float aa[8] = {a0.x, a0.y, a0.z, a0.w, a1.x, a1.y, a1.z, a1.w};
#pragma unroll
            for (int i = 0; i < 8; i++) {
                unsigned long long ap = pk2(aa[i], aa[i]);
                fma2(acc[i][0], ap, b0.x);
                fma2(acc[i][1], ap, b0.y);
                fma2(acc[i][2], ap, b1.x);
                fma2(acc[i][3], ap, b1.y);
            }
        }
        __syncthreads();
    }

    float4 bsa = *(const float4*)&bias[bn + tx * 8];
    float4 bsb = *(const float4*)&bias[bn + tx * 8 + 4];
#pragma unroll
    for (int i = 0; i < 8; i++) {
        float2 p0 = up2(acc[i][0]), p1 = up2(acc[i][1]);
        float2 p2 = up2(acc[i][2]), p3 = up2(acc[i][3]);
        float4 o0 = make_float4(p0.x + bsa.x, p0.y + bsa.y, p1.x + bsa.z, p1.y + bsa.w);
        float4 o1 = make_float4(p2.x + bsb.x, p2.y + bsb.y, p3.x + bsb.z, p3.y + bsb.w);
        size_t m = (size_t)(bm + ty * 8 + i);
        *(float4*)&C[m * N + bn + tx * 8]     = o0;
        *(float4*)&C[m * N + bn + tx * 8 + 4] = o1;
    }
}

// ---------------- mma.sync persistent LSTM scan (128 CTAs) ----------------
// 128 CTAs x 256 thr. CTA owns hidden cols [4cta, 4cta+4) -> 16 gate cols, n = g*4+q.
// Per step: gates[64,16] = h_hi@U_hi + h_lo@U_hi + h_hi@U_lo  (fp16 in, fp32 acc).
// 8 warps = (mg 2) x (kh 4); warp computes 2 m16-tiles x 2 n8-tiles over 8 kt/pass.
// A (h) is loaded exactly once per k-slice (no ng duplication).
// smem byte offsets:
#define SM_AH  0
#define SM_AL  66560
#define SM_UH  133120
#define SM_UL  149760
#define SM_GT  166400           // 4 x [64][PADC] f32 (kh partials)
#define SM_XP  186880           // [64][16] f32
#define SCAN_SMEM 190976

__global__ void __launch_bounds__(NTHR_SCAN, 1)
lstm_scan(const float* __restrict__ U, float* __restrict__ dout) {
    extern __shared__ char smem[];
    const uint32_t sb = smem_u32(smem);
    const int tid  = threadIdx.x;
    const int lane = tid & 31;
    const int wid  = tid >> 5;
    const int cta  = blockIdx.x;

    // ---- one-time: gather U slice -> hi/lo fp16 planes [n][k], pitch 520 ----
    for (int idx = tid; idx < 16 * 512; idx += NTHR_SCAN) {
        int n = idx & 15, k = idx >> 4;
        int g = n >> 2, q = n & 3;
        float u = U[(size_t)k * G4 + g * H_ + 4 * cta + q];
        __half uhi = __float2half_rn(u);
        __half ulo = __float2half_rn(u - __half2float(uhi));
        *(__half*)(smem + SM_UH + ((size_t)n * PITCH + k) * 2) = uhi;
        *(__half*)(smem + SM_UL + ((size_t)n * PITCH + k) * 2) = ulo;
    }

    // warp roles
    const int mg = wid & 1;     // m half: rows mg*32 .. mg*32+32
    const int kh = wid >> 1;    // k slice: kt in [kh*8, kh*8+8)

    // ldmatrix per-lane byte offsets (within a plane)
    // A: row = mg*32 + mi*16 + (lane&15); +16B if lane>=16 (k+8)
    uint32_t aoff[2];
#pragma unroll
    for (int mi = 0; mi < 2; mi++)
        aoff[mi] = (uint32_t)((mg * 32 + mi * 16 + (lane & 15)) * PITCH * 2 + (lane >> 4) * 16);
    // B x4 covers n16 x k16: sub = lane>>3: row = (sub>>1)*8 + (lane&7); +16B if sub&1
    const int sub = lane >> 3;
    const uint32_t boff = (uint32_t)(((sub >> 1) * 8 + (lane & 7)) * PITCH * 2 + (sub & 1) * 16);

    // cell-thread state: thread = (b,q): b = tid>>2, q = tid&3
    const int cb = tid >> 2, cq = tid & 3;
    const int hidx = 4 * cta + cq;
    float cst = 0.0f;
    const size_t OUT_ELEMS = (size_t)B_ * T_ * O_;

    __syncthreads();

    for (int s = 0; s < T_; s++) {
        // ---- stage h hi/lo planes: [b][512] fp16 -> smem pitch 520 ----
        {
            const uint4* s0 = (const uint4*)g_hhi[s & 1];
            const uint4* s1 = (const uint4*)g_hlo[s & 1];
#pragma unroll
            for (int i = 0; i < 16; i++) {
                int j = tid + i * NTHR_SCAN;           // 0..4095: row=j>>6, chunk=j&63
                uint32_t off = (uint32_t)((j >> 6) * (PITCH * 2) + (j & 63) * 16);
                *(uint4*)(smem + SM_AH + off) = __ldcg(&s0[j]);
                *(uint4*)(smem + SM_AL + off) = __ldcg(&s1[j]);
            }
        }
        // ---- xp -> smem [b][16] (one float4 per thread) ----
        {
            const float4* xs = (const float4*)(g_xp + ((size_t)cb * T_ + s) * G4 + (size_t)cq * H_ + 4 * cta);
            float4 v = __ldcg(xs);
            *(float4*)((float*)(smem + SM_XP) + cb * 16 + cq * 4) = v;
        }
        __syncthreads();

        // ---- 3 passes of m16n8k16 MMAs over this warp's 8 k-tiles ----
        float ac[16];
#pragma unroll
        for (int i = 0; i < 16; i++) ac[i] = 0.0f;

#pragma unroll
        for (int p = 0; p < 3; p++) {
            const uint32_t Ab = sb + ((p == 1) ? SM_AL : SM_AH);
            const uint32_t Bb = sb + ((p == 2) ? SM_UL : SM_UH);
            const int kt0 = kh * 8;
#pragma unroll
            for (int kt = kt0; kt < kt0 + 8; kt++) {
                uint32_t kb = (uint32_t)kt * 32;
                uint32_t a0[4], a1[4], bb[4];
                ldmx4(a0, Ab + aoff[0] + kb);
                ldmx4(a1, Ab + aoff[1] + kb);
                ldmx4(bb, Bb + boff + kb);
                mma16816(ac + 0,  a0, bb[0], bb[1]);   // (m0, n0)
                mma16816(ac + 4,  a0, bb[2], bb[3]);   // (m0, n1)
                mma16816(ac + 8,  a1, bb[0], bb[1]);   // (m1, n0)
                mma16816(ac + 12, a1, bb[2], bb[3]);   // (m1, n1)
            }
        }

        // ---- write kh-partials to gates smem ----
        {
            float* GT = (float*)(smem + SM_GT) + (size_t)kh * 64 * PADC;
            int r = lane >> 2, cbase = (lane & 3) * 2;
#pragma unroll
            for (int mi = 0; mi < 2; mi++)
#pragma unroll
                for (int ni = 0; ni < 2; ni++) {
                    const float* a = ac + mi * 8 + ni * 4;
                    int row = mg * 32 + mi * 16 + r;
                    int col = ni * 8 + cbase;
                    *(float2*)&GT[row * PADC + col]       = make_float2(a[0], a[1]);
                    *(float2*)&GT[(row + 8) * PADC + col] = make_float2(a[2], a[3]);
                }
        }
        __syncthreads();

        // ---- cell: 256 threads, one (b,q) each ----
        {
            const float* GT = (float*)(smem + SM_GT);
            const float* XP = (float*)(smem + SM_XP);
            float gt[4];
#pragma unroll
            for (int g = 0; g < 4; g++) {
                int col = g * 4 + cq;
                float v = XP[cb * 16 + col];
#pragma unroll
                for (int kk = 0; kk < 4; kk++)
                    v += GT[kk * 64 * PADC + cb * PADC + col];
                gt[g] = v;
            }
            float gi = sigmoidf_(gt[0]);
            float gf = sigmoidf_(gt[1]);
            float gg = tanhf(gt[2]);
            float go = sigmoidf_(gt[3]);
            float cn = gf * cst + gi * gg;
            cst = cn;
            float hn = go * tanhf(cn);

            g_hseq[((size_t)cb * T_ + s) * H_ + hidx] = hn;
            __half hh = __float2half_rn(hn);
            __half hl = __float2half_rn(hn - __half2float(hh));
            g_hhi[(s + 1) & 1][cb * H_ + hidx] = hh;
            g_hlo[(s + 1) & 1][cb * H_ + hidx] = hl;

            if (s == T_ - 1) {
                dout[OUT_ELEMS + (size_t)cb * H_ + hidx] = hn;
                dout[OUT_ELEMS + (size_t)B_ * H_ + (size_t)cb * H_ + hidx] = cn;
            }
        }

        // ---- grid barrier (128 CTAs, all resident) ----
        __threadfence();
        __syncthreads();
        if (tid == 0) {
            atomicAdd(&g_bar, 1u);
            unsigned target = (unsigned)NCTA_SCAN * (unsigned)(s + 1);
            while (*(volatile unsigned*)&g_bar < target) { }
            __threadfence();
        }
        __syncthreads();
    }
}

// ---------------- launch ----------------
extern "C" void kernel_launch(void* const* d_in, const int* in_sizes, int n_in,
                              void* d_out, int out_size) {
    const float* x    = (const float*)d_in[0];
    const float* W    = (const float*)d_in[1];
    const float* U    = (const float*)d_in[2];
    const float* bias = (const float*)d_in[3];
    const float* Wl   = (const float*)d_in[4];
    const float* bl   = (const float*)d_in[5];
    float* out = (float*)d_out;

    void* xp_ptr = nullptr;
    void* hs_ptr = nullptr;
    cudaGetSymbolAddress(&xp_ptr, g_xp);
    cudaGetSymbolAddress(&hs_ptr, g_hseq);

    cudaFuncSetAttribute(lstm_scan, cudaFuncAttributeMaxDynamicSharedMemorySize, SCAN_SMEM);

    // 1) reset h0 planes / barrier
    init_kernel<<<128, 256>>>();
    // 2) x_proj = x @ W + bias : [32768,256]@[256,2048]
    gemm_bias<<<dim3(G4 / 128, (B_ * T_) / 128), 256>>>(x, W, bias, (float*)xp_ptr,
                                                        B_ * T_, G4, I_);
    // 3) recurrent scan (mma.sync fp16-split, persistent, 512 steps)
    lstm_scan<<<NCTA_SCAN, NTHR_SCAN, SCAN_SMEM>>>(U, out);
    // 4) out = hidden_seq @ Wl + bl : [32768,512]@[512,256]
    gemm_bias<<<dim3(O_ / 128, (B_ * T_) / 128), 256>>>((const float*)hs_ptr, Wl, bl, out,
                                                        B_ * T_, O_, H_);
}

// round 13
// speedup vs baseline: 2.8781x; 1.1951x over previous
#include <cuda_runtime.h>
#include <cuda_fp16.h>
#include <cstdint>
#include <cstddef>

#define B_  64
#define T_  512
#define I_  256
#define H_  512
#define G4  2048   // 4*H
#define O_  256

#define NCTA_SCAN 128
#define NTHR_SCAN 256
#define PITCH 520          // fp16 pitch for mma operand tiles (65*16B rows -> conflict-free)
#define PADC  20           // gates smem col pad (16 + 4)

// ---------------- static scratch ----------------
__device__ float  g_xp[(size_t)B_ * T_ * G4];     // x@W + bias, [B*T, 4H]
__device__ float  g_hseq[(size_t)B_ * T_ * H_];   // hidden_seq [B*T, H]
__device__ __half g_hhi[2][B_ * H_];              // h fp16 plane, [b][k]
__device__ unsigned g_bar;

// ---------------- packed fp32x2 helpers (FFMA2, for the GEMMs) ----------------
__device__ __forceinline__ unsigned long long pk2(float x, float y) {
    unsigned long long r;
    asm("mov.b64 %0, {%1,%2};" : "=l"(r) : "f"(x), "f"(y));
    return r;
}
__device__ __forceinline__ void fma2(unsigned long long& d, unsigned long long a, unsigned long long b) {
    asm("fma.rn.f32x2 %0, %1, %2, %0;" : "+l"(d) : "l"(a), "l"(b));
}
__device__ __forceinline__ float2 up2(unsigned long long v) {
    float lo, hi;
    asm("mov.b64 {%0,%1}, %2;" : "=f"(lo), "=f"(hi) : "l"(v));
    return make_float2(lo, hi);
}
__device__ __forceinline__ float sigmoidf_(float x) { return 1.0f / (1.0f + expf(-x)); }

__device__ __forceinline__ uint32_t smem_u32(const void* p) {
    uint32_t a;
    asm("{ .reg .u64 t; cvta.to.shared.u64 t, %1; cvt.u32.u64 %0, t; }" : "=r"(a) : "l"(p));
    return a;
}
__device__ __forceinline__ void ldmx4(uint32_t* r, uint32_t addr) {
    asm volatile("ldmatrix.sync.aligned.m8n8.x4.shared.b16 {%0,%1,%2,%3}, [%4];"
                 : "=r"(r[0]), "=r"(r[1]), "=r"(r[2]), "=r"(r[3]) : "r"(addr));
}
__device__ __forceinline__ void mma16816(float* d, const uint32_t* a, uint32_t b0, uint32_t b1) {
    asm volatile(
        "mma.sync.aligned.m16n8k16.row.col.f32.f16.f16.f32 "
        "{%0,%1,%2,%3}, {%4,%5,%6,%7}, {%8,%9}, {%0,%1,%2,%3};"
        : "+f"(d[0]), "+f"(d[1]), "+f"(d[2]), "+f"(d[3])
        : "r"(a[0]), "r"(a[1]), "r"(a[2]), "r"(a[3]), "r"(b0), "r"(b1));
}

// ---------------- init ----------------
__global__ void init_kernel() {
    int i = blockIdx.x * blockDim.x + threadIdx.x;
    if (i < (B_ * H_) / 2) ((uint32_t*)g_hhi[0])[i] = 0u;
    if (i == 0) g_bar = 0u;
}

// ---------------- fp32 GEMM + bias (FFMA2), proven ----------------
__global__ void __launch_bounds__(256) gemm_bias(const float* __restrict__ A,
                                                 const float* __restrict__ Bm,
                                                 const float* __restrict__ bias,
                                                 float* __restrict__ C,
                                                 int M, int N, int K) {
    __shared__ float As[16][128];
    __shared__ float Bs[16][128];
    const int tid = threadIdx.x;
    const int bm = blockIdx.y * 128, bn = blockIdx.x * 128;
    const int tx = tid & 15, ty = tid >> 4;

    unsigned long long acc[8][4];
#pragma unroll
    for (int i = 0; i < 8; i++)
#pragma unroll
        for (int j = 0; j < 4; j++) acc[i][j] = 0ull;

    const int ar = tid >> 2, akq = tid & 3;
    const int br = tid >> 5, bc = tid & 31;

    for (int k0 = 0; k0 < K; k0 += 16) {
#pragma unroll
        for (int i = 0; i < 2; i++) {
            int r = ar + i * 64;
            float4 v = *(const float4*)&A[(size_t)(bm + r) * K + k0 + akq * 4];
            As[akq * 4 + 0][r] = v.x; As[akq * 4 + 1][r] = v.y;
            As[akq * 4 + 2][r] = v.z; As[akq * 4 + 3][r] = v.w;
        }
#pragma unroll
        for (int i = 0; i < 2; i++) {
            int rr = br + i * 8;
            *(float4*)&Bs[rr][bc * 4] =
                *(const float4*)&Bm[(size_t)(k0 + rr) * N + bn + bc * 4];
        }
        __syncthreads();
#pragma unroll
        for (int kk = 0; kk < 16; kk++) {
            float4 a0 = *(const float4*)&As[kk][ty * 8];
            float4 a1 = *(const float4*)&As[kk][ty * 8 + 4];
            ulonglong2 b0 = *(const ulonglong2*)&Bs[kk][tx * 8];
            ulonglong2 b1 = *(const ulonglong2*)&Bs[kk][tx * 8 + 4];
            float aa[8] = {a0.x, a0.y, a0.z, a0.w, a1.x, a1.y, a1.z, a1.w};
#pragma unroll
            for (int i = 0; i < 8; i++) {
                unsigned long long ap = pk2(aa[i], aa[i]);
                fma2(acc[i][0], ap, b0.x);
                fma2(acc[i][1], ap, b0.y);
                fma2(acc[i][2], ap, b1.x);
                fma2(acc[i][3], ap, b1.y);
            }
        }
        __syncthreads();
    }

    float4 bsa = *(const float4*)&bias[bn + tx * 8];
    float4 bsb = *(const float4*)&bias[bn + tx * 8 + 4];
#pragma unroll
    for (int i = 0; i < 8; i++) {
        float2 p0 = up2(acc[i][0]), p1 = up2(acc[i][1]);
        float2 p2 = up2(acc[i][2]), p3 = up2(acc[i][3]);
        float4 o0 = make_float4(p0.x + bsa.x, p0.y + bsa.y, p1.x + bsa.z, p1.y + bsa.w);
        float4 o1 = make_float4(p2.x + bsb.x, p2.y + bsb.y, p3.x + bsb.z, p3.y + bsb.w);
        size_t m = (size_t)(bm + ty * 8 + i);
        *(float4*)&C[m * N + bn + tx * 8]     = o0;
        *(float4*)&C[m * N + bn + tx * 8 + 4] = o1;
    }
}

// ---------------- mma.sync persistent LSTM scan (128 CTAs, fp16 h, split U) ----------------
// 128 CTAs x 256 thr. CTA owns hidden cols [4cta, 4cta+4) -> 16 gate cols, n = g*4+q.
// Per step: gates[64,16] = h_f16 @ (U_hi + U_lo)  (fp16 in, fp32 acc, shared accumulators).
// 8 warps = (mg 2) x (kh 4); per kt: 2 A-ldmx4 + 2 B-ldmx4 (hi,lo) + 8 mma.
// smem byte offsets:
#define SM_AH  0
#define SM_UH  66560
#define SM_UL  83200
#define SM_GT  99840            // 4 x [64][PADC] f32 (kh partials)
#define SM_XP  120320           // [64][16] f32
#define SCAN_SMEM 124416

__global__ void __launch_bounds__(NTHR_SCAN, 1)
lstm_scan(const float* __restrict__ U, float* __restrict__ dout) {
    extern __shared__ char smem[];
    const uint32_t sb = smem_u32(smem);
    const int tid  = threadIdx.x;
    const int lane = tid & 31;
    const int wid  = tid >> 5;
    const int cta  = blockIdx.x;

    // ---- one-time: gather U slice -> hi/lo fp16 planes [n][k], pitch 520 ----
    for (int idx = tid; idx < 16 * 512; idx += NTHR_SCAN) {
        int n = idx & 15, k = idx >> 4;
        int g = n >> 2, q = n & 3;
        float u = U[(size_t)k * G4 + g * H_ + 4 * cta + q];
        __half uhi = __float2half_rn(u);
        __half ulo = __float2half_rn(u - __half2float(uhi));
        *(__half*)(smem + SM_UH + ((size_t)n * PITCH + k) * 2) = uhi;
        *(__half*)(smem + SM_UL + ((size_t)n * PITCH + k) * 2) = ulo;
    }

    // warp roles
    const int mg = wid & 1;     // m half: rows mg*32 .. mg*32+32
    const int kh = wid >> 1;    // k slice: kt in [kh*8, kh*8+8)

    // ldmatrix per-lane byte offsets (within a plane)
    uint32_t aoff[2];
#pragma unroll
    for (int mi = 0; mi < 2; mi++)
        aoff[mi] = (uint32_t)((mg * 32 + mi * 16 + (lane & 15)) * PITCH * 2 + (lane >> 4) * 16);
    const int sub = lane >> 3;
    const uint32_t boff = (uint32_t)(((sub >> 1) * 8 + (lane & 7)) * PITCH * 2 + (sub & 1) * 16);

    // cell-thread state: thread = (b,q): b = tid>>2, q = tid&3
    const int cb = tid >> 2, cq = tid & 3;
    const int hidx = 4 * cta + cq;
    float cst = 0.0f;
    const size_t OUT_ELEMS = (size_t)B_ * T_ * O_;

    // xp prefetch for step 0
    float4 xpre = __ldcg((const float4*)(g_xp + ((size_t)cb * T_ + 0) * G4 + (size_t)cq * H_ + 4 * cta));

    __syncthreads();

    for (int s = 0; s < T_; s++) {
        // ---- stage h plane: [b][512] fp16 -> smem pitch 520 ----
        {
            const uint4* s0 = (const uint4*)g_hhi[s & 1];
#pragma unroll
            for (int i = 0; i < 16; i++) {
                int j = tid + i * NTHR_SCAN;           // 0..4095: row=j>>6, chunk=j&63
                uint32_t off = (uint32_t)((j >> 6) * (PITCH * 2) + (j & 63) * 16);
                *(uint4*)(smem + SM_AH + off) = __ldcg(&s0[j]);
            }
        }
        // ---- xp (prefetched) -> smem [b][16] ----
        *(float4*)((float*)(smem + SM_XP) + cb * 16 + cq * 4) = xpre;
        __syncthreads();

        // ---- MMA: 8 k-tiles, A loaded once, both U planes into shared accumulators ----
        float ac[16];
#pragma unroll
        for (int i = 0; i < 16; i++) ac[i] = 0.0f;
        {
            const uint32_t Ab  = sb + SM_AH;
            const uint32_t BHb = sb + SM_UH;
            const uint32_t BLb = sb + SM_UL;
            const int kt0 = kh * 8;
#pragma unroll
            for (int kt = kt0; kt < kt0 + 8; kt++) {
                uint32_t kb = (uint32_t)kt * 32;
                uint32_t a0[4], a1[4], bh[4], bl[4];
                ldmx4(a0, Ab + aoff[0] + kb);
                ldmx4(a1, Ab + aoff[1] + kb);
                ldmx4(bh, BHb + boff + kb);
                ldmx4(bl, BLb + boff + kb);
                mma16816(ac + 0,  a0, bh[0], bh[1]);
                mma16816(ac + 4,  a0, bh[2], bh[3]);
                mma16816(ac + 8,  a1, bh[0], bh[1]);
                mma16816(ac + 12, a1, bh[2], bh[3]);
                mma16816(ac + 0,  a0, bl[0], bl[1]);
                mma16816(ac + 4,  a0, bl[2], bl[3]);
                mma16816(ac + 8,  a1, bl[0], bl[1]);
                mma16816(ac + 12, a1, bl[2], bl[3]);
            }
        }

        // ---- write kh-partials to gates smem ----
        {
            float* GT = (float*)(smem + SM_GT) + (size_t)kh * 64 * PADC;
            int r = lane >> 2, cbase = (lane & 3) * 2;
#pragma unroll
            for (int mi = 0; mi < 2; mi++)
#pragma unroll
                for (int ni = 0; ni < 2; ni++) {
                    const float* a = ac + mi * 8 + ni * 4;
                    int row = mg * 32 + mi * 16 + r;
                    int col = ni * 8 + cbase;
                    *(float2*)&GT[row * PADC + col]       = make_float2(a[0], a[1]);
                    *(float2*)&GT[(row + 8) * PADC + col] = make_float2(a[2], a[3]);
                }
        }
        __syncthreads();

        // ---- cell: 256 threads, one (b,q) each ----
        {
            const float* GT = (float*)(smem + SM_GT);
            const float* XP = (float*)(smem + SM_XP);
            float gt[4];
#pragma unroll
            for (int g = 0; g < 4; g++) {
                int col = g * 4 + cq;
                float v = XP[cb * 16 + col];
#pragma unroll
                for (int kk = 0; kk < 4; kk++)
                    v += GT[kk * 64 * PADC + cb * PADC + col];
                gt[g] = v;
            }
            float gi = sigmoidf_(gt[0]);
            float gf = sigmoidf_(gt[1]);
            float gg = tanhf(gt[2]);
            float go = sigmoidf_(gt[3]);
            float cn = gf * cst + gi * gg;
            cst = cn;
            float hn = go * tanhf(cn);

            g_hseq[((size_t)cb * T_ + s) * H_ + hidx] = hn;
            g_hhi[(s + 1) & 1][cb * H_ + hidx] = __float2half_rn(hn);

            if (s == T_ - 1) {
                dout[OUT_ELEMS + (size_t)cb * H_ + hidx] = hn;
                dout[OUT_ELEMS + (size_t)B_ * H_ + (size_t)cb * H_ + hidx] = cn;
            }
        }

        // ---- grid barrier with xp prefetch hidden in the wait window ----
        __threadfence();
        __syncthreads();
        if (tid == 0) atomicAdd(&g_bar, 1u);
        if (s + 1 < T_)
            xpre = __ldcg((const float4*)(g_xp + ((size_t)cb * T_ + (s + 1)) * G4 + (size_t)cq * H_ + 4 * cta));
        if (tid == 0) {
            unsigned target = (unsigned)NCTA_SCAN * (unsigned)(s + 1);
            while (*(volatile unsigned*)&g_bar < target) { }
            __threadfence();
        }
        __syncthreads();
    }
}

// ---------------- launch ----------------
extern "C" void kernel_launch(void* const* d_in, const int* in_sizes, int n_in,
                              void* d_out, int out_size) {
    const float* x    = (const float*)d_in[0];
    const float* W    = (const float*)d_in[1];
    const float* U    = (const float*)d_in[2];
    const float* bias = (const float*)d_in[3];
    const float* Wl   = (const float*)d_in[4];
    const float* bl   = (const float*)d_in[5];
    float* out = (float*)d_out;

    void* xp_ptr = nullptr;
    void* hs_ptr = nullptr;
    cudaGetSymbolAddress(&xp_ptr, g_xp);
    cudaGetSymbolAddress(&hs_ptr, g_hseq);

    cudaFuncSetAttribute(lstm_scan, cudaFuncAttributeMaxDynamicSharedMemorySize, SCAN_SMEM);

    // 1) reset h0 plane / barrier
    init_kernel<<<128, 256>>>();
    // 2) x_proj = x @ W + bias : [32768,256]@[256,2048]
    gemm_bias<<<dim3(G4 / 128, (B_ * T_) / 128), 256>>>(x, W, bias, (float*)xp_ptr,
                                                        B_ * T_, G4, I_);
    // 3) recurrent scan (mma.sync, fp16 h + split U, persistent, 512 steps)
    lstm_scan<<<NCTA_SCAN, NTHR_SCAN, SCAN_SMEM>>>(U, out);
    // 4) out = hidden_seq @ Wl + bl : [32768,512]@[512,256]
    gemm_bias<<<dim3(O_ / 128, (B_ * T_) / 128), 256>>>((const float*)hs_ptr, Wl, bl, out,
                                                        B_ * T_, O_, H_);
}

// round 14
// speedup vs baseline: 2.9949x; 1.0406x over previous
#include <cuda_runtime.h>
#include <cuda_fp16.h>
#include <cstdint>
#include <cstddef>

#define B_  64
#define T_  512
#define I_  256
#define H_  512
#define G4  2048   // 4*H
#define O_  256

#define NCTA_SCAN 128
#define NTHR_SCAN 256
#define PITCH 520          // fp16 pitch for mma operand tiles (65*16B rows -> conflict-free)
#define PADC  20           // gates smem col pad (16 + 4)

// ---------------- static scratch ----------------
__device__ float  g_xp[(size_t)B_ * T_ * G4];     // x@W + bias, [B*T, 4H]
__device__ float  g_hseq[(size_t)B_ * T_ * H_];   // hidden_seq [B*T, H]
__device__ __half g_hhi[2][B_ * H_];              // h fp16 plane, [b][k]
__device__ unsigned g_bar;

// ---------------- packed fp32x2 helpers (FFMA2, for the GEMMs) ----------------
__device__ __forceinline__ unsigned long long pk2(float x, float y) {
    unsigned long long r;
    asm("mov.b64 %0, {%1,%2};" : "=l"(r) : "f"(x), "f"(y));
    return r;
}
__device__ __forceinline__ void fma2(unsigned long long& d, unsigned long long a, unsigned long long b) {
    asm("fma.rn.f32x2 %0, %1, %2, %0;" : "+l"(d) : "l"(a), "l"(b));
}
__device__ __forceinline__ float2 up2(unsigned long long v) {
    float lo, hi;
    asm("mov.b64 {%0,%1}, %2;" : "=f"(lo), "=f"(hi) : "l"(v));
    return make_float2(lo, hi);
}
__device__ __forceinline__ float sigmoidf_(float x) { return 1.0f / (1.0f + expf(-x)); }

__device__ __forceinline__ uint32_t smem_u32(const void* p) {
    uint32_t a;
    asm("{ .reg .u64 t; cvta.to.shared.u64 t, %1; cvt.u32.u64 %0, t; }" : "=r"(a) : "l"(p));
    return a;
}
__device__ __forceinline__ void ldmx4(uint32_t* r, uint32_t addr) {
    asm volatile("ldmatrix.sync.aligned.m8n8.x4.shared.b16 {%0,%1,%2,%3}, [%4];"
                 : "=r"(r[0]), "=r"(r[1]), "=r"(r[2]), "=r"(r[3]) : "r"(addr));
}
__device__ __forceinline__ void mma16816(float* d, const uint32_t* a, uint32_t b0, uint32_t b1) {
    asm volatile(
        "mma.sync.aligned.m16n8k16.row.col.f32.f16.f16.f32 "
        "{%0,%1,%2,%3}, {%4,%5,%6,%7}, {%8,%9}, {%0,%1,%2,%3};"
        : "+f"(d[0]), "+f"(d[1]), "+f"(d[2]), "+f"(d[3])
        : "r"(a[0]), "r"(a[1]), "r"(a[2]), "r"(a[3]), "r"(b0), "r"(b1));
}
__device__ __forceinline__ void cpasync16(uint32_t dst, const void* src) {
    asm volatile("cp.async.cg.shared.global [%0], [%1], 16;" :: "r"(dst), "l"(src) : "memory");
}

// ---------------- init ----------------
__global__ void init_kernel() {
    int i = blockIdx.x * blockDim.x + threadIdx.x;
    if (i < (B_ * H_) / 2) ((uint32_t*)g_hhi[0])[i] = 0u;
    if (i == 0) g_bar = 0u;
}

// ---------------- fp32 GEMM + bias (FFMA2), proven ----------------
__global__ void __launch_bounds__(256) gemm_bias(const float* __restrict__ A,
                                                 const float* __restrict__ Bm,
                                                 const float* __restrict__ bias,
                                                 float* __restrict__ C,
                                                 int M, int N, int K) {
    __shared__ float As[16][128];
    __shared__ float Bs[16][128];
    const int tid = threadIdx.x;
    const int bm = blockIdx.y * 128, bn = blockIdx.x * 128;
    const int tx = tid & 15, ty = tid >> 4;

    unsigned long long acc[8][4];
#pragma unroll
    for (int i = 0; i < 8; i++)
#pragma unroll
        for (int j = 0; j < 4; j++) acc[i][j] = 0ull;

    const int ar = tid >> 2, akq = tid & 3;
    const int br = tid >> 5, bc = tid & 31;

    for (int k0 = 0; k0 < K; k0 += 16) {
#pragma unroll
        for (int i = 0; i < 2; i++) {
            int r = ar + i * 64;
            float4 v = *(const float4*)&A[(size_t)(bm + r) * K + k0 + akq * 4];
            As[akq * 4 + 0][r] = v.x; As[akq * 4 + 1][r] = v.y;
            As[akq * 4 + 2][r] = v.z; As[akq * 4 + 3][r] = v.w;
        }
#pragma unroll
        for (int i = 0; i < 2; i++) {
            int rr = br + i * 8;
            *(float4*)&Bs[rr][bc * 4] =
                *(const float4*)&Bm[(size_t)(k0 + rr) * N + bn + bc * 4];
        }
        __syncthreads();
#pragma unroll
        for (int kk = 0; kk < 16; kk++) {
            float4 a0 = *(const float4*)&As[kk][ty * 8];
            float4 a1 = *(const float4*)&As[kk][ty * 8 + 4];
            ulonglong2 b0 = *(const ulonglong2*)&Bs[kk][tx * 8];
            ulonglong2 b1 = *(const ulonglong2*)&Bs[kk][tx * 8 + 4];
            float aa[8] = {a0.x, a0.y, a0.z, a0.w, a1.x, a1.y, a1.z, a1.w};
#pragma unroll
            for (int i = 0; i < 8; i++) {
                unsigned long long ap = pk2(aa[i], aa[i]);
                fma2(acc[i][0], ap, b0.x);
                fma2(acc[i][1], ap, b0.y);
                fma2(acc[i][2], ap, b1.x);
                fma2(acc[i][3], ap, b1.y);
            }
        }
        __syncthreads();
    }

    float4 bsa = *(const float4*)&bias[bn + tx * 8];
    float4 bsb = *(const float4*)&bias[bn + tx * 8 + 4];
#pragma unroll
    for (int i = 0; i < 8; i++) {
        float2 p0 = up2(acc[i][0]), p1 = up2(acc[i][1]);
        float2 p2 = up2(acc[i][2]), p3 = up2(acc[i][3]);
        float4 o0 = make_float4(p0.x + bsa.x, p0.y + bsa.y, p1.x + bsa.z, p1.y + bsa.w);
        float4 o1 = make_float4(p2.x + bsb.x, p2.y + bsb.y, p3.x + bsb.z, p3.y + bsb.w);
        size_t m = (size_t)(bm + ty * 8 + i);
        *(float4*)&C[m * N + bn + tx * 8]     = o0;
        *(float4*)&C[m * N + bn + tx * 8 + 4] = o1;
    }
}

// ---------------- mma.sync persistent LSTM scan (128 CTAs, fp16 h, split U) ----------------
// 128 CTAs x 256 thr. CTA owns hidden cols [4cta, 4cta+4) -> 16 gate cols, n = g*4+q.
// Per step: gates[64,16] = h_f16 @ (U_hi + U_lo)  (fp16 in, fp32 acc, shared accumulators).
// 8 warps = (mg 2) x (kh 4); per kt: 2 A-ldmx4 + 2 B-ldmx4 (hi,lo) + 8 mma.
// Grid barrier: CG-style release-atomic arrive + acquire poll (no MEMBAR.ALL.GPU).
// h staging: cp.async.cg (L2 -> smem direct).
// smem byte offsets:
#define SM_AH  0
#define SM_UH  66560
#define SM_UL  83200
#define SM_GT  99840            // 4 x [64][PADC] f32 (kh partials)
#define SM_XP  120320           // [64][16] f32
#define SCAN_SMEM 124416

__global__ void __launch_bounds__(NTHR_SCAN, 1)
lstm_scan(const float* __restrict__ U, float* __restrict__ dout) {
    extern __shared__ char smem[];
    const uint32_t sb = smem_u32(smem);
    const int tid  = threadIdx.x;
    const int lane = tid & 31;
    const int wid  = tid >> 5;
    const int cta  = blockIdx.x;

    // ---- one-time: gather U slice -> hi/lo fp16 planes [n][k], pitch 520 ----
    for (int idx = tid; idx < 16 * 512; idx += NTHR_SCAN) {
        int n = idx & 15, k = idx >> 4;
        int g = n >> 2, q = n & 3;
        float u = U[(size_t)k * G4 + g * H_ + 4 * cta + q];
        __half uhi = __float2half_rn(u);
        __half ulo = __float2half_rn(u - __half2float(uhi));
        *(__half*)(smem + SM_UH + ((size_t)n * PITCH + k) * 2) = uhi;
        *(__half*)(smem + SM_UL + ((size_t)n * PITCH + k) * 2) = ulo;
    }

    // warp roles
    const int mg = wid & 1;     // m half: rows mg*32 .. mg*32+32
    const int kh = wid >> 1;    // k slice: kt in [kh*8, kh*8+8)

    // ldmatrix per-lane byte offsets (within a plane)
    uint32_t aoff[2];
#pragma unroll
    for (int mi = 0; mi < 2; mi++)
        aoff[mi] = (uint32_t)((mg * 32 + mi * 16 + (lane & 15)) * PITCH * 2 + (lane >> 4) * 16);
    const int sub = lane >> 3;
    const uint32_t boff = (uint32_t)(((sub >> 1) * 8 + (lane & 7)) * PITCH * 2 + (sub & 1) * 16);

    // cell-thread state: thread = (b,q): b = tid>>2, q = tid&3
    const int cb = tid >> 2, cq = tid & 3;
    const int hidx = 4 * cta + cq;
    float cst = 0.0f;
    const size_t OUT_ELEMS = (size_t)B_ * T_ * O_;

    // precomputed staging addresses: 16 cp.async of 16B per thread
    uint32_t sdst[16];
    uint32_t ssrc_off[16];      // byte offset within the h plane
#pragma unroll
    for (int i = 0; i < 16; i++) {
        int j = tid + i * NTHR_SCAN;                 // 0..4095: row=j>>6, chunk=j&63
        sdst[i] = sb + SM_AH + (uint32_t)((j >> 6) * (PITCH * 2) + (j & 63) * 16);
        ssrc_off[i] = (uint32_t)j * 16;
    }

    // xp prefetch for step 0
    float4 xpre = __ldcg((const float4*)(g_xp + ((size_t)cb * T_ + 0) * G4 + (size_t)cq * H_ + 4 * cta));

    __syncthreads();

    for (int s = 0; s < T_; s++) {
        // ---- stage h plane via cp.async (L2 -> smem) ----
        {
            const char* src = (const char*)g_hhi[s & 1];
#pragma unroll
            for (int i = 0; i < 16; i++)
                cpasync16(sdst[i], src + ssrc_off[i]);
            asm volatile("cp.async.commit_group;");
        }
        // ---- xp (prefetched) -> smem [b][16] ----
        *(float4*)((float*)(smem + SM_XP) + cb * 16 + cq * 4) = xpre;
        asm volatile("cp.async.wait_group 0;" ::: "memory");
        __syncthreads();

        // ---- MMA: 8 k-tiles, A loaded once, both U planes into shared accumulators ----
        float ac[16];
#pragma unroll
        for (int i = 0; i < 16; i++) ac[i] = 0.0f;
        {
            const uint32_t Ab  = sb + SM_AH;
            const uint32_t BHb = sb + SM_UH;
            const uint32_t BLb = sb + SM_UL;
            const int kt0 = kh * 8;
#pragma unroll
            for (int kt = kt0; kt < kt0 + 8; kt++) {
                uint32_t kb = (uint32_t)kt * 32;
                uint32_t a0[4], a1[4], bh[4], bl[4];
                ldmx4(a0, Ab + aoff[0] + kb);
                ldmx4(a1, Ab + aoff[1] + kb);
                ldmx4(bh, BHb + boff + kb);
                ldmx4(bl, BLb + boff + kb);
                mma16816(ac + 0,  a0, bh[0], bh[1]);
                mma16816(ac + 4,  a0, bh[2], bh[3]);
                mma16816(ac + 8,  a1, bh[0], bh[1]);
                mma16816(ac + 12, a1, bh[2], bh[3]);
                mma16816(ac + 0,  a0, bl[0], bl[1]);
                mma16816(ac + 4,  a0, bl[2], bl[3]);
                mma16816(ac + 8,  a1, bl[0], bl[1]);
                mma16816(ac + 12, a1, bl[2], bl[3]);
            }
        }

        // ---- write kh-partials to gates smem ----
        {
            float* GT = (float*)(smem + SM_GT) + (size_t)kh * 64 * PADC;
            int r = lane >> 2, cbase = (lane & 3) * 2;
#pragma unroll
            for (int mi = 0; mi < 2; mi++)
#pragma unroll
                for (int ni = 0; ni < 2; ni++) {
                    const float* a = ac + mi * 8 + ni * 4;
                    int row = mg * 32 + mi * 16 + r;
                    int col = ni * 8 + cbase;
                    *(float2*)&GT[row * PADC + col]       = make_float2(a[0], a[1]);
                    *(float2*)&GT[(row + 8) * PADC + col] = make_float2(a[2], a[3]);
                }
        }
        __syncthreads();

        // ---- cell: 256 threads, one (b,q) each ----
        {
            const float* GT = (float*)(smem + SM_GT);
            const float* XP = (float*)(smem + SM_XP);
            float gt[4];
#pragma unroll
            for (int g = 0; g < 4; g++) {
                int col = g * 4 + cq;
                float v = XP[cb * 16 + col];
#pragma unroll
                for (int kk = 0; kk < 4; kk++)
                    v += GT[kk * 64 * PADC + cb * PADC + col];
                gt[g] = v;
            }
            float gi = sigmoidf_(gt[0]);
            float gf = sigmoidf_(gt[1]);
            float gg = tanhf(gt[2]);
            float go = sigmoidf_(gt[3]);
            float cn = gf * cst + gi * gg;
            cst = cn;
            float hn = go * tanhf(cn);

            g_hseq[((size_t)cb * T_ + s) * H_ + hidx] = hn;
            g_hhi[(s + 1) & 1][cb * H_ + hidx] = __float2half_rn(hn);

            if (s == T_ - 1) {
                dout[OUT_ELEMS + (size_t)cb * H_ + hidx] = hn;
                dout[OUT_ELEMS + (size_t)B_ * H_ + (size_t)cb * H_ + hidx] = cn;
            }
        }

        // ---- grid barrier: release arrive + acquire poll (CG-style, no MEMBAR.ALL) ----
        __syncthreads();                     // h writes by all threads done
        if (tid == 0)
            asm volatile("red.release.gpu.global.add.u32 [%0], 1;" :: "l"(&g_bar) : "memory");
        if (s + 1 < T_)
            xpre = __ldcg((const float4*)(g_xp + ((size_t)cb * T_ + (s + 1)) * G4 + (size_t)cq * H_ + 4 * cta));
        if (tid == 0) {
            unsigned target = (unsigned)NCTA_SCAN * (unsigned)(s + 1);
            unsigned v;
            do {
                asm volatile("ld.acquire.gpu.global.u32 %0, [%1];" : "=r"(v) : "l"(&g_bar) : "memory");
            } while (v < target);
        }
        __syncthreads();                     // all threads ordered after acquire
    }
}

// ---------------- launch ----------------
extern "C" void kernel_launch(void* const* d_in, const int* in_sizes, int n_in,
                              void* d_out, int out_size) {
    const float* x    = (const float*)d_in[0];
    const float* W    = (const float*)d_in[1];
    const float* U    = (const float*)d_in[2];
    const float* bias = (const float*)d_in[3];
    const float* Wl   = (const float*)d_in[4];
    const float* bl   = (const float*)d_in[5];
    float* out = (float*)d_out;

    void* xp_ptr = nullptr;
    void* hs_ptr = nullptr;
    cudaGetSymbolAddress(&xp_ptr, g_xp);
    cudaGetSymbolAddress(&hs_ptr, g_hseq);

    cudaFuncSetAttribute(lstm_scan, cudaFuncAttributeMaxDynamicSharedMemorySize, SCAN_SMEM);

    // 1) reset h0 plane / barrier
    init_kernel<<<128, 256>>>();
    // 2) x_proj = x @ W + bias : [32768,256]@[256,2048]
    gemm_bias<<<dim3(G4 / 128, (B_ * T_) / 128), 256>>>(x, W, bias, (float*)xp_ptr,
                                                        B_ * T_, G4, I_);
    // 3) recurrent scan (mma.sync, fp16 h + split U, persistent, 512 steps)
    lstm_scan<<<NCTA_SCAN, NTHR_SCAN, SCAN_SMEM>>>(U, out);
    // 4) out = hidden_seq @ Wl + bl : [32768,512]@[512,256]
    gemm_bias<<<dim3(O_ / 128, (B_ * T_) / 128), 256>>>((const float*)hs_ptr, Wl, bl, out,
                                                        B_ * T_, O_, H_);
}